// round 5
// baseline (speedup 1.0000x reference)
#include <cuda_runtime.h>
#include <cstdint>

// PixelShuffle (depth-to-space, R=2, feature-major grouping)
// in : [B=8, X=256, Y=256, C=256] fp32,  C = F*4, c = f*4 + i*2 + j
// out: [B=8, 2X=512, 2Y=512, F=64] fp32
// out[b, 2x+i, 2y+j, f] = in[b, x, y, 4f + 2i + j]
//
// One thread per (b,x,y,f): a single aligned float4 load delivers the four
// output-pixel values for feature f; four coalesced scalar stores scatter them.

static constexpr int B = 8;
static constexpr int X = 256;
static constexpr int Y = 256;
static constexpr int F = 64;

__global__ __launch_bounds__(256, 8)
void pixel_shuffle_kernel(const float4* __restrict__ in, float* __restrict__ out) {
    // tid layout: f fastest (6 bits), then y (8), x (8), b (3)
    const uint32_t tid = blockIdx.x * 256u + threadIdx.x;   // < B*X*Y*F = 33,554,432

    const uint32_t f   = tid & 63u;
    const uint32_t pix = tid >> 6;            // (b*X + x)*Y + y
    const uint32_t y   = pix & 255u;
    const uint32_t x   = (pix >> 8) & 255u;
    const uint32_t b   = pix >> 16;

    // Input: ((b*X+x)*Y+y)*256 + 4f floats == pix*64 + f float4s. Streaming load.
    const float4 v = __ldcs(in + (pix << 6) + f);

    // Output rows: xr = 2x (+1), cols yr = 2y (+1); row stride 512*64 floats.
    const uint32_t base00 = (((b << 9) + (x << 1)) << 9 | (y << 1)) * 64u + f;
    //            = ((b*512 + 2x)*512 + 2y)*64 + f
    const uint32_t rowStride = 512u * 64u;

    __stcs(out + base00,                  v.x);  // (i=0, j=0)
    __stcs(out + base00 + 64u,            v.y);  // (i=0, j=1)
    __stcs(out + base00 + rowStride,      v.z);  // (i=1, j=0)
    __stcs(out + base00 + rowStride + 64, v.w);  // (i=1, j=1)
}

extern "C" void kernel_launch(void* const* d_in, const int* in_sizes, int n_in,
                              void* d_out, int out_size) {
    const float4* in  = (const float4*)d_in[0];
    float*        out = (float*)d_out;

    const uint32_t total  = (uint32_t)B * X * Y * F;   // 33,554,432 threads
    const uint32_t blocks = total / 256u;              // 131,072
    pixel_shuffle_kernel<<<blocks, 256>>>(in, out);
}